// round 6
// baseline (speedup 1.0000x reference)
#include <cuda_runtime.h>
#include <cuda_bf16.h>
#include <cstdint>
#include <cstddef>

#define N_NODES 100000
#define N_EDGES_MAX 1600000
#define D 128
#define SLD 768            // scratch row: [h(0:128) | beta(128:256) | gamma(256:384) | skip(384:512) | beta_s(512:640) | gamma_s(640:768)]
#define NLAYERS 4

// ---------------- device scratch (no allocations allowed) ----------------
__device__ __align__(16) float g_scratch[(size_t)N_NODES * SLD];
__device__ __align__(16) float g_xbuf0[(size_t)N_NODES * D];
__device__ __align__(16) float g_xbuf1[(size_t)N_NODES * D];
__device__ __align__(16) float g_agg[(size_t)N_NODES * D];
__device__ int   g_deg[N_NODES];
__device__ int   g_off[N_NODES + 1];
__device__ int   g_cursor[N_NODES];
__device__ int   g_csr[N_EDGES_MAX];
__device__ int   g_bsum[128];
__device__ int   g_idx32;          // 1 => edge_index stored as int32, 0 => int64
// split weights: [L][768][128] bf16, n-major (k contiguous); bias [L][768]
__device__ __align__(16) __nv_bfloat16 g_wt_hi[NLAYERS * 768 * 128];
__device__ __align__(16) __nv_bfloat16 g_wt_lo[NLAYERS * 768 * 128];
__device__ __align__(16) float g_bias[NLAYERS * 768];

// ---------------- helpers ----------------
__device__ __forceinline__ uint32_t smem_u32(const void* p) {
    uint32_t a;
    asm("{ .reg .u64 t; cvta.to.shared.u64 t, %1; cvt.u32.u64 %0, t; }" : "=r"(a) : "l"(p));
    return a;
}

#define LDSM_X4(r, addr) \
    asm volatile("ldmatrix.sync.aligned.m8n8.x4.shared.b16 {%0,%1,%2,%3}, [%4];" \
                 : "=r"((r)[0]), "=r"((r)[1]), "=r"((r)[2]), "=r"((r)[3]) : "r"(addr))
#define LDSM_X2(r, addr) \
    asm volatile("ldmatrix.sync.aligned.m8n8.x2.shared.b16 {%0,%1}, [%2];" \
                 : "=r"((r)[0]), "=r"((r)[1]) : "r"(addr))

__device__ __forceinline__ void mma_bf16(float* c, const uint32_t* a, const uint32_t* b) {
    asm volatile("mma.sync.aligned.m16n8k16.row.col.f32.bf16.bf16.f32 "
                 "{%0,%1,%2,%3}, {%4,%5,%6,%7}, {%8,%9}, {%0,%1,%2,%3};"
                 : "+f"(c[0]), "+f"(c[1]), "+f"(c[2]), "+f"(c[3])
                 : "r"(a[0]), "r"(a[1]), "r"(a[2]), "r"(a[3]), "r"(b[0]), "r"(b[1]));
}

// ---------------- edge index dtype detection (JAX demotes int64->int32) ----------------
__global__ void k_detect(const void* __restrict__ ei, int E)
{
    const long long* p = (const long long*)ei;
    int n = E < 4096 ? E : 4096;
    int is32 = 0;
    for (int i = 0; i < n; i++) {
        long long v = p[i];
        if (v < 0 || v >= N_NODES) { is32 = 1; break; }
    }
    g_idx32 = is32;
}
__device__ __forceinline__ int load_edge(const void* ei, int idx, int mode)
{
    if (mode) return ((const int*)ei)[idx];
    return (int)((const long long*)ei)[idx];
}

// ---------------- weight prep: concat + transpose + bf16 hi/lo split ----------------
// Wt[l][n][k]: n<128 W_lin | 128..383 W_film | 384..511 W_skip | 512..767 W_fskip
__global__ void k_prep_weights(const float* __restrict__ W_lin, const float* __restrict__ W_film,
                               const float* __restrict__ b_film, const float* __restrict__ W_skip,
                               const float* __restrict__ W_fskip)
{
    const int total = NLAYERS * 768 * 128;
    for (int idx = blockIdx.x * blockDim.x + threadIdx.x; idx < total; idx += gridDim.x * blockDim.x) {
        int k = idx & 127;
        int n = (idx >> 7) % 768;
        int l = idx / (768 * 128);
        float v;
        if (n < 128)       v = W_lin[((size_t)l * 128 + k) * 128 + n];
        else if (n < 384)  v = W_film[((size_t)l * 128 + k) * 256 + (n - 128)];
        else if (n < 512)  v = W_skip[((size_t)l * 128 + k) * 128 + (n - 384)];
        else               v = W_fskip[((size_t)l * 128 + k) * 256 + (n - 512)];
        __nv_bfloat16 hi = __float2bfloat16(v);
        __nv_bfloat16 lo = __float2bfloat16(v - __bfloat162float(hi));
        g_wt_hi[idx] = hi;
        g_wt_lo[idx] = lo;
        if (k == 0)
            g_bias[l * 768 + n] = (n >= 128 && n < 384) ? b_film[l * 256 + (n - 128)] : 0.0f;
    }
}

// ---------------- HMMA GEMM: C[m0:+128, colOff+n0:+128] = A @ Wt^T (+bias), ld(C)=SLD ----------------
// bf16x3 split via mma.sync.m16n8k16 (baseline PTX, valid at compute_100).
// Whi/Wlo/bias passed pre-offset by colOff; colOff only shifts the C column base.
#define PITCHB 272                       // bytes per smem row (136 bf16)
#define SM_AHI 0
#define SM_ALO (128 * PITCHB)
#define SM_BHI (2 * 128 * PITCHB)
#define SM_BLO (3 * 128 * PITCHB)
#define SMEM_HM (4 * 128 * PITCHB + 16)  // 139280

__global__ __launch_bounds__(256, 1)
void hmma_gemm(const float* __restrict__ A, const __nv_bfloat16* __restrict__ Whi,
               const __nv_bfloat16* __restrict__ Wlo, const float* __restrict__ bias,
               float* __restrict__ C, int M, int colOff)
{
    extern __shared__ char smem[];
    const uint32_t sb = smem_u32(smem);

    const int tid  = threadIdx.x;
    const int wid  = tid >> 5;
    const int lane = tid & 31;
    const int m0 = blockIdx.x * 128;
    const int n0 = blockIdx.y * 128;
    const int wm = (wid >> 1) * 32;
    const int wn = (wid & 1) * 64;

    // ---- load A (128x128 fp32), split bf16 hi/lo into SMEM ----
    #pragma unroll
    for (int it = 0; it < 16; it++) {
        int idx = tid + it * 256;
        int row = idx >> 5;
        int kq  = (idx & 31) << 2;
        float4 v = make_float4(0.f, 0.f, 0.f, 0.f);
        if (m0 + row < M)
            v = *(const float4*)(A + (size_t)(m0 + row) * D + kq);
        __nv_bfloat16 h0 = __float2bfloat16(v.x), h1 = __float2bfloat16(v.y),
                      h2 = __float2bfloat16(v.z), h3 = __float2bfloat16(v.w);
        __nv_bfloat16 l0 = __float2bfloat16(v.x - __bfloat162float(h0)),
                      l1 = __float2bfloat16(v.y - __bfloat162float(h1)),
                      l2 = __float2bfloat16(v.z - __bfloat162float(h2)),
                      l3 = __float2bfloat16(v.w - __bfloat162float(h3));
        uint32_t off = (uint32_t)(row * PITCHB + kq * 2);
        uint2 hp, lp;
        hp.x = (uint32_t)__bfloat16_as_ushort(h0) | ((uint32_t)__bfloat16_as_ushort(h1) << 16);
        hp.y = (uint32_t)__bfloat16_as_ushort(h2) | ((uint32_t)__bfloat16_as_ushort(h3) << 16);
        lp.x = (uint32_t)__bfloat16_as_ushort(l0) | ((uint32_t)__bfloat16_as_ushort(l1) << 16);
        lp.y = (uint32_t)__bfloat16_as_ushort(l2) | ((uint32_t)__bfloat16_as_ushort(l3) << 16);
        *(uint2*)(smem + SM_AHI + off) = hp;
        *(uint2*)(smem + SM_ALO + off) = lp;
    }

    // ---- load B hi/lo (128 n-rows x 128 k bf16) into SMEM ----
    #pragma unroll
    for (int it = 0; it < 8; it++) {
        int idx = tid + it * 256;
        int n  = idx >> 4;
        int k8 = (idx & 15) << 3;
        size_t srci = (size_t)(n0 + n) * 128 + k8;
        uint32_t off = (uint32_t)(n * PITCHB + k8 * 2);
        *(uint4*)(smem + SM_BHI + off) = *(const uint4*)(Whi + srci);
        *(uint4*)(smem + SM_BLO + off) = *(const uint4*)(Wlo + srci);
    }
    __syncthreads();

    // ---- mainloop: 8 k-steps x (2 mtiles x 8 ntiles) x 3 mma ----
    float acc[2][8][4];
    #pragma unroll
    for (int mt = 0; mt < 2; mt++)
        #pragma unroll
        for (int nt = 0; nt < 8; nt++)
            #pragma unroll
            for (int j = 0; j < 4; j++) acc[mt][nt][j] = 0.f;

    const uint32_t aAddrH = sb + SM_AHI + (uint32_t)((wm + (lane & 15)) * PITCHB + ((lane >> 4) * 8) * 2);
    const uint32_t aAddrL = aAddrH + (SM_ALO - SM_AHI);
    const uint32_t bAddrH = sb + SM_BHI + (uint32_t)((wn + (lane & 7)) * PITCHB + (((lane >> 3) & 1) * 8) * 2);
    const uint32_t bAddrL = bAddrH + (SM_BLO - SM_BHI);

    #pragma unroll
    for (int kt = 0; kt < 8; kt++) {
        const uint32_t ko = kt * 32;
        uint32_t ah[2][4], al[2][4];
        #pragma unroll
        for (int mt = 0; mt < 2; mt++) {
            LDSM_X4(ah[mt], aAddrH + mt * 16 * PITCHB + ko);
            LDSM_X4(al[mt], aAddrL + mt * 16 * PITCHB + ko);
        }
        uint32_t bh[8][2], bl[8][2];
        #pragma unroll
        for (int nt = 0; nt < 8; nt++) {
            LDSM_X2(bh[nt], bAddrH + nt * 8 * PITCHB + ko);
            LDSM_X2(bl[nt], bAddrL + nt * 8 * PITCHB + ko);
        }
        #pragma unroll
        for (int mt = 0; mt < 2; mt++)
            #pragma unroll
            for (int nt = 0; nt < 8; nt++) {
                mma_bf16(acc[mt][nt], ah[mt], bh[nt]);
                mma_bf16(acc[mt][nt], ah[mt], bl[nt]);
                mma_bf16(acc[mt][nt], al[mt], bh[nt]);
            }
    }

    // ---- epilogue: scatter accumulators + bias to C (ld=SLD) ----
    const int r0 = lane >> 2;
    const int c0 = (lane & 3) * 2;
    #pragma unroll
    for (int mt = 0; mt < 2; mt++) {
        #pragma unroll
        for (int nt = 0; nt < 8; nt++) {
            int colB = wn + nt * 8 + c0;
            float2 b2 = *(const float2*)(bias + n0 + colB);
            #pragma unroll
            for (int p = 0; p < 2; p++) {
                int row = m0 + wm + mt * 16 + r0 + p * 8;
                if (row < M) {
                    float2 o;
                    o.x = acc[mt][nt][p * 2 + 0] + b2.x;
                    o.y = acc[mt][nt][p * 2 + 1] + b2.y;
                    *(float2*)(C + (size_t)row * SLD + colOff + n0 + colB) = o;
                }
            }
        }
    }
}

// ---------------- graph setup kernels ----------------
__global__ void k_deg(const void* __restrict__ ei, int E)
{
    const int mode = g_idx32;
    for (int i = blockIdx.x * blockDim.x + threadIdx.x; i < E; i += gridDim.x * blockDim.x) {
        int d = load_edge(ei, E + i, mode);
        atomicAdd(&g_deg[d], 1);
    }
}

__global__ void k_scan1()
{
    __shared__ int s[1024];
    int tid = threadIdx.x;
    int i = blockIdx.x * 1024 + tid;
    s[tid] = (i < N_NODES) ? g_deg[i] : 0;
    __syncthreads();
    #pragma unroll
    for (int d = 512; d > 0; d >>= 1) {
        if (tid < d) s[tid] += s[tid + d];
        __syncthreads();
    }
    if (tid == 0) g_bsum[blockIdx.x] = s[0];
}

__global__ void k_scan2(int nb)
{
    int run = 0;
    for (int b = 0; b < nb; b++) {
        int v = g_bsum[b];
        g_bsum[b] = run;
        run += v;
    }
    g_off[N_NODES] = run;
}

__global__ void k_scan3()
{
    __shared__ int s[1024];
    int tid = threadIdx.x;
    int i = blockIdx.x * 1024 + tid;
    int v = (i < N_NODES) ? g_deg[i] : 0;
    s[tid] = v;
    __syncthreads();
    #pragma unroll
    for (int d = 1; d < 1024; d <<= 1) {
        int t = (tid >= d) ? s[tid - d] : 0;
        __syncthreads();
        s[tid] += t;
        __syncthreads();
    }
    int excl = s[tid] - v;
    int base = g_bsum[blockIdx.x];
    if (i < N_NODES) {
        g_off[i]    = base + excl;
        g_cursor[i] = base + excl;
    }
}

__global__ void k_scatter(const void* __restrict__ ei, int E)
{
    const int mode = g_idx32;
    for (int i = blockIdx.x * blockDim.x + threadIdx.x; i < E; i += gridDim.x * blockDim.x) {
        int d = load_edge(ei, E + i, mode);
        int s = load_edge(ei, i, mode);
        int pos = atomicAdd(&g_cursor[d], 1);
        g_csr[pos] = s;
    }
}

// ---------------- edge aggregation: agg[dst] = mean(relu(gamma[dst]*h[src]+beta[dst])) ----------------
// one warp per dst node; lane handles 4 channels; 4x unrolled gather for MLP
__global__ __launch_bounds__(256)
void edge_agg_kernel(const float* __restrict__ scratch, float* __restrict__ agg)
{
    int warp = (blockIdx.x * blockDim.x + threadIdx.x) >> 5;
    int lane = threadIdx.x & 31;
    if (warp >= N_NODES) return;

    const float* base = scratch + (size_t)warp * SLD;
    const int c = lane * 4;

    float4 beta  = *(const float4*)(base + 128 + c);
    float4 gamma = *(const float4*)(base + 256 + c);

    const int s0 = g_off[warp], s1 = g_off[warp + 1];
    float4 a0 = make_float4(0.f, 0.f, 0.f, 0.f);
    float4 a1 = make_float4(0.f, 0.f, 0.f, 0.f);
    float4 a2 = make_float4(0.f, 0.f, 0.f, 0.f);
    float4 a3 = make_float4(0.f, 0.f, 0.f, 0.f);

    int i = s0;
    for (; i + 4 <= s1; i += 4) {
        int sA = g_csr[i], sB = g_csr[i + 1], sC = g_csr[i + 2], sD = g_csr[i + 3];
        float4 hA = __ldg((const float4*)(scratch + (size_t)sA * SLD + c));
        float4 hB = __ldg((const float4*)(scratch + (size_t)sB * SLD + c));
        float4 hC = __ldg((const float4*)(scratch + (size_t)sC * SLD + c));
        float4 hD = __ldg((const float4*)(scratch + (size_t)sD * SLD + c));
        a0.x += fmaxf(fmaf(gamma.x, hA.x, beta.x), 0.f);
        a0.y += fmaxf(fmaf(gamma.y, hA.y, beta.y), 0.f);
        a0.z += fmaxf(fmaf(gamma.z, hA.z, beta.z), 0.f);
        a0.w += fmaxf(fmaf(gamma.w, hA.w, beta.w), 0.f);
        a1.x += fmaxf(fmaf(gamma.x, hB.x, beta.x), 0.f);
        a1.y += fmaxf(fmaf(gamma.y, hB.y, beta.y), 0.f);
        a1.z += fmaxf(fmaf(gamma.z, hB.z, beta.z), 0.f);
        a1.w += fmaxf(fmaf(gamma.w, hB.w, beta.w), 0.f);
        a2.x += fmaxf(fmaf(gamma.x, hC.x, beta.x), 0.f);
        a2.y += fmaxf(fmaf(gamma.y, hC.y, beta.y), 0.f);
        a2.z += fmaxf(fmaf(gamma.z, hC.z, beta.z), 0.f);
        a2.w += fmaxf(fmaf(gamma.w, hC.w, beta.w), 0.f);
        a3.x += fmaxf(fmaf(gamma.x, hD.x, beta.x), 0.f);
        a3.y += fmaxf(fmaf(gamma.y, hD.y, beta.y), 0.f);
        a3.z += fmaxf(fmaf(gamma.z, hD.z, beta.z), 0.f);
        a3.w += fmaxf(fmaf(gamma.w, hD.w, beta.w), 0.f);
    }
    for (; i < s1; i++) {
        int sA = g_csr[i];
        float4 hA = __ldg((const float4*)(scratch + (size_t)sA * SLD + c));
        a0.x += fmaxf(fmaf(gamma.x, hA.x, beta.x), 0.f);
        a0.y += fmaxf(fmaf(gamma.y, hA.y, beta.y), 0.f);
        a0.z += fmaxf(fmaf(gamma.z, hA.z, beta.z), 0.f);
        a0.w += fmaxf(fmaf(gamma.w, hA.w, beta.w), 0.f);
    }
    float dinv = 1.0f / fmaxf((float)(s1 - s0), 1.0f);
    float4 r;
    r.x = ((a0.x + a1.x) + (a2.x + a3.x)) * dinv;
    r.y = ((a0.y + a1.y) + (a2.y + a3.y)) * dinv;
    r.z = ((a0.z + a1.z) + (a2.z + a3.z)) * dinv;
    r.w = ((a0.w + a1.w) + (a2.w + a3.w)) * dinv;
    *(float4*)(agg + (size_t)warp * D + c) = r;
}

// ---------------- combine: x = relu(gs*skip+bs) + agg  (+ inter-layer relu) ----------------
__global__ __launch_bounds__(256)
void k_combine(const float* __restrict__ scratch, const float* __restrict__ agg,
               float* __restrict__ xout, int applyRelu)
{
    int t = blockIdx.x * blockDim.x + threadIdx.x;
    int node = t >> 5;
    if (node >= N_NODES) return;
    int c = (t & 31) * 4;
    const float* base = scratch + (size_t)node * SLD;

    float4 skip = *(const float4*)(base + 384 + c);
    float4 bs   = *(const float4*)(base + 512 + c);
    float4 gs   = *(const float4*)(base + 640 + c);
    float4 a    = *(const float4*)(agg + (size_t)node * D + c);

    float4 r;
    r.x = fmaxf(fmaf(gs.x, skip.x, bs.x), 0.f) + a.x;
    r.y = fmaxf(fmaf(gs.y, skip.y, bs.y), 0.f) + a.y;
    r.z = fmaxf(fmaf(gs.z, skip.z, bs.z), 0.f) + a.z;
    r.w = fmaxf(fmaf(gs.w, skip.w, bs.w), 0.f) + a.w;
    if (applyRelu) {
        r.x = fmaxf(r.x, 0.f);
        r.y = fmaxf(r.y, 0.f);
        r.z = fmaxf(r.z, 0.f);
        r.w = fmaxf(r.w, 0.f);
    }
    *(float4*)(xout + (size_t)node * D + c) = r;
}

// ---------------- host launch ----------------
extern "C" void kernel_launch(void* const* d_in, const int* in_sizes, int n_in,
                              void* d_out, int out_size)
{
    const float* x_in    = (const float*)d_in[0];
    const void*  ei      = d_in[1];
    const float* W_lin   = (const float*)d_in[2];
    const float* W_film  = (const float*)d_in[3];
    const float* b_film  = (const float*)d_in[4];
    const float* W_skip  = (const float*)d_in[5];
    const float* W_fskip = (const float*)d_in[6];
    const int E = in_sizes[1] / 2;

    float *scratch, *x0, *x1, *agg, *bias;
    int *deg;
    __nv_bfloat16 *whi, *wlo;
    cudaGetSymbolAddress((void**)&scratch, g_scratch);
    cudaGetSymbolAddress((void**)&x0, g_xbuf0);
    cudaGetSymbolAddress((void**)&x1, g_xbuf1);
    cudaGetSymbolAddress((void**)&agg, g_agg);
    cudaGetSymbolAddress((void**)&deg, g_deg);
    cudaGetSymbolAddress((void**)&whi, g_wt_hi);
    cudaGetSymbolAddress((void**)&wlo, g_wt_lo);
    cudaGetSymbolAddress((void**)&bias, g_bias);

    cudaFuncSetAttribute(hmma_gemm, cudaFuncAttributeMaxDynamicSharedMemorySize, SMEM_HM);

    // streams/events: created fresh each call (cheap host objects; capture turns
    // record/wait into graph edges, so the objects aren't referenced at replay).
    cudaStream_t s2;
    cudaStreamCreateWithFlags(&s2, cudaStreamNonBlocking);
    cudaEvent_t evRoot, evCsr, evG1[NLAYERS], evG2[NLAYERS];
    cudaEventCreateWithFlags(&evRoot, cudaEventDisableTiming);
    cudaEventCreateWithFlags(&evCsr, cudaEventDisableTiming);
    for (int l = 0; l < NLAYERS; l++) {
        cudaEventCreateWithFlags(&evG1[l], cudaEventDisableTiming);
        cudaEventCreateWithFlags(&evG2[l], cudaEventDisableTiming);
    }

    const int NB = (N_NODES + 1023) / 1024;   // 98
    const int MB = (N_NODES + 127) / 128;     // 782
    float* out = (float*)d_out;

    // ---- fork: main stream preps weights; s2 builds CSR concurrently ----
    cudaEventRecord(evRoot, 0);
    cudaStreamWaitEvent(s2, evRoot, 0);

    k_prep_weights<<<512, 256>>>(W_lin, W_film, b_film, W_skip, W_fskip);

    k_detect<<<1, 1, 0, s2>>>(ei, E);
    cudaMemsetAsync(deg, 0, N_NODES * sizeof(int), s2);
    k_deg<<<1024, 256, 0, s2>>>(ei, E);
    k_scan1<<<NB, 1024, 0, s2>>>();
    k_scan2<<<1, 1, 0, s2>>>(NB);
    k_scan3<<<NB, 1024, 0, s2>>>();
    k_scatter<<<1024, 256, 0, s2>>>(ei, E);
    cudaEventRecord(evCsr, s2);

    for (int l = 0; l < NLAYERS; l++) {
        const float* A  = (l == 0) ? x_in : ((l % 2 == 0) ? x1 : x0);
        float*       xo = (l == NLAYERS - 1) ? out : ((l % 2 == 0) ? x0 : x1);
        const __nv_bfloat16* whiL = whi + (size_t)l * 768 * 128;
        const __nv_bfloat16* wloL = wlo + (size_t)l * 768 * 128;
        const float* biasL = bias + l * 768;

        // G1: cols 0-384 (h, beta, gamma) on main stream
        hmma_gemm<<<dim3(MB, 3), 256, SMEM_HM>>>(A, whiL, wloL, biasL, scratch, N_NODES, 0);
        cudaEventRecord(evG1[l], 0);

        // G2: cols 384-768 (skip, beta_s, gamma_s) on s2, concurrent with edge_agg
        cudaStreamWaitEvent(s2, evG1[l], 0);
        hmma_gemm<<<dim3(MB, 3), 256, SMEM_HM, s2>>>(
            A, whiL + (size_t)384 * 128, wloL + (size_t)384 * 128, biasL + 384,
            scratch, N_NODES, 384);
        cudaEventRecord(evG2[l], s2);

        // edge aggregation on main stream (needs CSR once, then null-stream order)
        if (l == 0) cudaStreamWaitEvent(0, evCsr, 0);
        edge_agg_kernel<<<(N_NODES + 7) / 8, 256>>>(scratch, agg);

        // combine after both edge (null-order) and G2 (event)
        cudaStreamWaitEvent(0, evG2[l], 0);
        k_combine<<<(N_NODES * 32 + 255) / 256, 256>>>(scratch, agg, xo, l < NLAYERS - 1 ? 1 : 0);
    }
}